// round 10
// baseline (speedup 1.0000x reference)
#include <cuda_runtime.h>
#include <math.h>

#define T1V 257
#define BATCH 512
#define SDV 128
#define ADV 32
#define HSV 512
#define SFV 256
#define R2 131072    // 256*512 rows
#define RALL 131584  // 257*512 rows

// ---------------- scratch (__device__ globals; no runtime allocation) ----------------
__device__ float g_feats [(size_t)T1V * BATCH * HSV];       // 257x512x512
__device__ float g_xw    [(size_t)RALL * 1024];             // feats@Wih0^T + bih0
__device__ float g_outs  [(size_t)T1V * BATCH * SFV];       // h1 history (257 slots)
__device__ float g_h0hist[(size_t)(T1V + 1) * BATCH * SFV]; // h0 history, slot0 = zeros
__device__ float g_pred  [(size_t)256 * BATCH * SFV];
__device__ float g_hidA  [(size_t)R2 * HSV];
__device__ float g_hidB  [(size_t)R2 * HSV];
__device__ float g_c0    [BATCH * SFV];
__device__ float g_c1    [BATCH * SFV];
__device__ float g_pfl   [2048];
__device__ float g_pil   [512];

__device__ __forceinline__ float sigmoidf_(float x) { return 1.0f / (1.0f + expf(-x)); }

// ---------------- init: zero c0,c1 and h0hist slot 0 ----------------
__global__ void init_kernel() {
    int i = blockIdx.x * blockDim.x + threadIdx.x;  // 131072
    g_c0[i] = 0.f; g_c1[i] = 0.f;
    g_h0hist[i] = 0.f;
}

// ---------------- fused LSTM step: L0(s0) + L1(s1) in ONE balanced launch ----------
// Grid 384 CTAs, 256 threads, static smem ~10KB -> single wave (<=3 CTAs/SM).
//  CTAs 0..127  : layer0 step s0. Tile 64 batch x 16 units (K=256, masked h0 @ Whh0; xw added in epilogue)
//  CTAs 128..383: layer1 step s1. Tile 32 batch x 16 units (K=512: h0' @ Wih1 + masked h1 @ Whh1)
// Equal work per CTA: 64*64*256 = 32*64*512 = 1.05 MFMA.
#define KCR 16
__global__ __launch_bounds__(256) void lstm_fused(
    int s0, int s1,
    float* __restrict__ h0hist,          // 258 slots
    const float* __restrict__ xw,
    float* __restrict__ outs,            // 257 slots
    float* __restrict__ c0, float* __restrict__ c1,
    const float* __restrict__ Whh0, const float* __restrict__ bhh0,
    const float* __restrict__ Wih1, const float* __restrict__ Whh1,
    const float* __restrict__ bih1, const float* __restrict__ bhh1,
    const int* __restrict__ dones,
    float* __restrict__ hid)
{
    __shared__ float as_[KCR][76];
    __shared__ float ws_[KCR][76];
    __shared__ float msk[64];
    const int tid = threadIdx.x;

    if (blockIdx.x < 128) {
        // ================= LAYER 0 =================
        if (s0 < 0) return;
        const int b0 = (blockIdx.x >> 4) << 6;   // 8 tiles of 64 batch
        const int u0 = (blockIdx.x & 15) << 4;   // 16 tiles of 16 units
        const int ui = tid & 15;
        const int bq = tid >> 4;          // 0..15
        const int lrow = tid >> 2;        // 0..63
        const int lk = (tid & 3) * 4;
        const int* done = dones + (size_t)s0 * BATCH;

        if (tid < 64) msk[tid] = 1.f - (float)done[b0 + tid];
        __syncthreads();

        float acc[4][4];
#pragma unroll
        for (int i = 0; i < 4; i++)
#pragma unroll
            for (int g = 0; g < 4; g++) acc[i][g] = 0.f;

        const int wrow = ((lrow >> 4) << 8) + u0 + (lrow & 15);  // gate*256 + unit
        const float mrow = msk[lrow];
        const float* xr = h0hist + (size_t)s0 * 131072 + (size_t)(b0 + lrow) * SFV;
        const float* wr = Whh0 + (size_t)wrow * SFV;
        for (int kc = 0; kc < SFV; kc += KCR) {
            float4 xv = *(const float4*)(xr + kc + lk);
            float4 wv = *(const float4*)(wr + kc + lk);
            as_[lk + 0][lrow] = xv.x * mrow; as_[lk + 1][lrow] = xv.y * mrow;
            as_[lk + 2][lrow] = xv.z * mrow; as_[lk + 3][lrow] = xv.w * mrow;
            ws_[lk + 0][lrow] = wv.x; ws_[lk + 1][lrow] = wv.y;
            ws_[lk + 2][lrow] = wv.z; ws_[lk + 3][lrow] = wv.w;
            __syncthreads();
#pragma unroll
            for (int k = 0; k < KCR; k++) {
                float4 a4 = *(const float4*)&as_[k][bq << 2];
                float w0 = ws_[k][ui], w1 = ws_[k][16 + ui];
                float w2 = ws_[k][32 + ui], w3 = ws_[k][48 + ui];
                acc[0][0] += a4.x * w0; acc[0][1] += a4.x * w1; acc[0][2] += a4.x * w2; acc[0][3] += a4.x * w3;
                acc[1][0] += a4.y * w0; acc[1][1] += a4.y * w1; acc[1][2] += a4.y * w2; acc[1][3] += a4.y * w3;
                acc[2][0] += a4.z * w0; acc[2][1] += a4.z * w1; acc[2][2] += a4.z * w2; acc[2][3] += a4.z * w3;
                acc[3][0] += a4.w * w0; acc[3][1] += a4.w * w1; acc[3][2] += a4.w * w2; acc[3][3] += a4.w * w3;
            }
            __syncthreads();
        }

        // epilogue: 4 batches x 1 unit, xw input-gates added here
        const int u = u0 + ui;
        float* cst = c0;
        float* h_out = h0hist + (size_t)(s0 + 1) * 131072;
        float* hh = (s0 == 256) ? hid : nullptr;
        float* hc = (s0 == 256) ? hid + 262144 : nullptr;
        float bsum[4];
#pragma unroll
        for (int g = 0; g < 4; g++) bsum[g] = bhh0[(g << 8) + u];
#pragma unroll
        for (int i = 0; i < 4; i++) {
            const int bl = (bq << 2) + i;
            const int b = b0 + bl;
            const float* xr2 = xw + (size_t)s0 * 524288 + (size_t)b * 1024 + u;
            float ig = sigmoidf_(acc[i][0] + bsum[0] + xr2[0]);
            float fg = sigmoidf_(acc[i][1] + bsum[1] + xr2[256]);
            float gg = tanhf(acc[i][2] + bsum[2] + xr2[512]);
            float og = sigmoidf_(acc[i][3] + bsum[3] + xr2[768]);
            const float m = msk[bl];
            const int idx = b * SFV + u;
            float c2 = fg * (cst[idx] * m) + ig * gg;
            float h2 = og * tanhf(c2);
            cst[idx] = c2;
            h_out[idx] = h2;
            if (hh) { hh[idx] = h2; hc[idx] = c2; }
        }
    } else {
        // ================= LAYER 1 =================
        if (s1 < 0) return;
        const int blk = blockIdx.x - 128;
        const int b0 = (blk >> 4) << 5;   // 16 tiles of 32 batch
        const int u0 = (blk & 15) << 4;   // 16 tiles of 16 units
        const int ui = tid & 15;
        const int bq = tid >> 4;          // 0..15 (batch pair)
        const int arow = tid >> 3;        // 0..31
        const int ak = (tid & 7) << 1;    // 0,2,..,14
        const int wrow = tid >> 2;        // 0..63
        const int lk = (tid & 3) * 4;
        const int* done = dones + (size_t)s1 * BATCH;

        if (tid < 32) msk[tid] = 1.f - (float)done[b0 + tid];
        __syncthreads();

        float acc[2][4];
#pragma unroll
        for (int i = 0; i < 2; i++)
#pragma unroll
            for (int g = 0; g < 4; g++) acc[i][g] = 0.f;

        const int wgrow = ((wrow >> 4) << 8) + u0 + (wrow & 15);  // gate*256 + unit

#pragma unroll
        for (int ph = 0; ph < 2; ph++) {
            const float* A; const float* W; float mrow;
            if (ph == 0) {
                A = h0hist + (size_t)(s1 + 1) * 131072;  // h0' (this step's L0 output, prev launch)
                W = Wih1; mrow = 1.f;
            } else {
                A = (s1 == 0) ? h0hist /*slot0 zeros*/ : outs + (size_t)(s1 - 1) * 131072;
                W = Whh1; mrow = msk[arow];
            }
            const float* ar = A + (size_t)(b0 + arow) * SFV + ak;
            const float* wr = W + (size_t)wgrow * SFV + lk;
            for (int kc = 0; kc < SFV; kc += KCR) {
                float2 av = *(const float2*)(ar + kc);
                float4 wv = *(const float4*)(wr + kc);
                as_[ak + 0][arow] = av.x * mrow;
                as_[ak + 1][arow] = av.y * mrow;
                ws_[lk + 0][wrow] = wv.x; ws_[lk + 1][wrow] = wv.y;
                ws_[lk + 2][wrow] = wv.z; ws_[lk + 3][wrow] = wv.w;
                __syncthreads();
#pragma unroll
                for (int k = 0; k < KCR; k++) {
                    float2 a2 = *(const float2*)&as_[k][bq << 1];
                    float w0 = ws_[k][ui], w1 = ws_[k][16 + ui];
                    float w2 = ws_[k][32 + ui], w3 = ws_[k][48 + ui];
                    acc[0][0] += a2.x * w0; acc[0][1] += a2.x * w1; acc[0][2] += a2.x * w2; acc[0][3] += a2.x * w3;
                    acc[1][0] += a2.y * w0; acc[1][1] += a2.y * w1; acc[1][2] += a2.y * w2; acc[1][3] += a2.y * w3;
                }
                __syncthreads();
            }
        }

        // epilogue: 2 batches x 1 unit
        const int u = u0 + ui;
        float* cst = c1;
        float* h_out = outs + (size_t)s1 * 131072;
        float* hh = (s1 == 256) ? hid + 131072 : nullptr;
        float* hc = (s1 == 256) ? hid + 393216 : nullptr;
        float bsum[4];
#pragma unroll
        for (int g = 0; g < 4; g++) bsum[g] = bih1[(g << 8) + u] + bhh1[(g << 8) + u];
#pragma unroll
        for (int i = 0; i < 2; i++) {
            const int bl = (bq << 1) + i;
            const int b = b0 + bl;
            float ig = sigmoidf_(acc[i][0] + bsum[0]);
            float fg = sigmoidf_(acc[i][1] + bsum[1]);
            float gg = tanhf(acc[i][2] + bsum[2]);
            float og = sigmoidf_(acc[i][3] + bsum[3]);
            const float m = msk[bl];
            const int idx = b * SFV + u;
            float c2 = fg * (cst[idx] * m) + ig * gg;
            float h2 = og * tanhf(c2);
            cst[idx] = c2;
            h_out[idx] = h2;
            if (hh) { hh[idx] = h2; hc[idx] = c2; }
        }
    }
}

// ---------------- generic SGEMM: C = act(A @ W^T + bias) ----------------
#define KC 16
template <int ACT>
__global__ __launch_bounds__(256) void gemm_kernel(
    const float* __restrict__ A1, int K1,
    const float* __restrict__ A2,
    const float* __restrict__ W,
    const float* __restrict__ bias,
    float* __restrict__ C,
    int M, int N, int K)
{
    __shared__ float as_[KC][132];
    __shared__ float bs_[KC][132];
    const int m0 = blockIdx.x * 128;
    const int n0 = blockIdx.y * 128;
    const int tid = threadIdx.x;
    const int mi = tid >> 4;
    const int ni = tid & 15;
    const int lrow = tid >> 2;
    const int lk = (tid & 3) * 4;

    float acc[8][8];
#pragma unroll
    for (int i = 0; i < 8; i++)
#pragma unroll
        for (int j = 0; j < 8; j++) acc[i][j] = 0.f;

    for (int kc = 0; kc < K; kc += KC) {
        const float* Asrc;
        int Ak, koff;
        if (kc < K1) { Asrc = A1; Ak = K1; koff = kc; }
        else         { Asrc = A2; Ak = K - K1; koff = kc - K1; }
#pragma unroll
        for (int r = 0; r < 2; r++) {
            int row = lrow + r * 64;
            float4 v = *(const float4*)(Asrc + (size_t)(m0 + row) * Ak + koff + lk);
            as_[lk + 0][row] = v.x; as_[lk + 1][row] = v.y;
            as_[lk + 2][row] = v.z; as_[lk + 3][row] = v.w;
            float4 w = *(const float4*)(W + (size_t)(n0 + row) * K + kc + lk);
            bs_[lk + 0][row] = w.x; bs_[lk + 1][row] = w.y;
            bs_[lk + 2][row] = w.z; bs_[lk + 3][row] = w.w;
        }
        __syncthreads();
#pragma unroll
        for (int k = 0; k < KC; k++) {
            float4 a0 = *(const float4*)&as_[k][mi * 8];
            float4 a1 = *(const float4*)&as_[k][mi * 8 + 4];
            float a[8] = {a0.x, a0.y, a0.z, a0.w, a1.x, a1.y, a1.z, a1.w};
            float b[8];
#pragma unroll
            for (int j = 0; j < 8; j++) b[j] = bs_[k][ni + j * 16];
#pragma unroll
            for (int i = 0; i < 8; i++)
#pragma unroll
                for (int j = 0; j < 8; j++) acc[i][j] += a[i] * b[j];
        }
        __syncthreads();
    }
#pragma unroll
    for (int i = 0; i < 8; i++) {
        int row = m0 + mi * 8 + i;
#pragma unroll
        for (int j = 0; j < 8; j++) {
            int col = n0 + ni + j * 16;
            float v = acc[i][j] + bias[col];
            if (ACT == 1) v = fmaxf(v, 0.f);
            C[(size_t)row * N + col] = v;
        }
    }
}

// ---------------- forward loss + intrinsic reward ----------------
__global__ void floss_kernel(const float* __restrict__ pred, const float* __restrict__ outs,
                             float* __restrict__ intr, float* __restrict__ pfl)
{
    const int w = threadIdx.x >> 5, lane = threadIdx.x & 31;
    const int r0 = blockIdx.x * 64;
    __shared__ float sred[8];
    float wacc = 0.f;
    for (int p = 0; p < 8; p++) {
        int r = r0 + p * 8 + w;
        const float4* pp = (const float4*)(pred + (size_t)r * SFV) + lane * 2;
        const float4* np = (const float4*)(outs + (size_t)(r + BATCH) * SFV) + lane * 2;
        float4 p0 = pp[0], p1 = pp[1], n0 = np[0], n1 = np[1];
        float d0 = p0.x - n0.x, d1 = p0.y - n0.y, d2 = p0.z - n0.z, d3 = p0.w - n0.w;
        float d4 = p1.x - n1.x, d5 = p1.y - n1.y, d6 = p1.z - n1.z, d7 = p1.w - n1.w;
        float s = d0 * d0 + d1 * d1 + d2 * d2 + d3 * d3 + d4 * d4 + d5 * d5 + d6 * d6 + d7 * d7;
#pragma unroll
        for (int o = 16; o; o >>= 1) s += __shfl_xor_sync(0xffffffffu, s, o);
        if (lane == 0) { intr[r] = s; wacc += s; }
    }
    if (lane == 0) sred[w] = wacc;
    __syncthreads();
    if (threadIdx.x == 0) {
        float t = 0.f;
        for (int i = 0; i < 8; i++) t += sred[i];
        pfl[blockIdx.x] = t;
    }
}

// ---------------- inverse head: mu/std + NLL partials ----------------
__global__ void inv_kernel(const float* __restrict__ hm, const float* __restrict__ hs,
                           const float* __restrict__ Wm2, const float* __restrict__ bm2,
                           const float* __restrict__ Ws2, const float* __restrict__ bs2,
                           const float* __restrict__ act, float* __restrict__ pil)
{
    extern __shared__ float sh[];
    float* wm = sh;
    float* ws2s = sh + 16384;
    float* bm = sh + 32768;
    float* bs = sh + 32800;
    float* red = sh + 32832;
    const int tid = threadIdx.x;
    for (int idx = tid; idx < 16384; idx += 256) {
        int d = idx & 31, k = idx >> 5;
        wm[idx] = Wm2[(size_t)d * HSV + k];
        ws2s[idx] = Ws2[(size_t)d * HSV + k];
    }
    if (tid < 32) { bm[tid] = bm2[tid]; bs[tid] = bs2[tid]; }
    __syncthreads();

    const int w = tid >> 5, lane = tid & 31;
    const int r0 = blockIdx.x * 256;
    float ilacc = 0.f;
    for (int p = 0; p < 32; p++) {
        int r = r0 + p * 8 + w;
        const float4* h4m = (const float4*)(hm + (size_t)r * HSV);
        const float4* h4s = (const float4*)(hs + (size_t)r * HSV);
        float am = 0.f, as2 = 0.f;
#pragma unroll 4
        for (int k4 = 0; k4 < 128; k4++) {
            float4 a = h4m[k4];
            float4 b = h4s[k4];
            int kb = k4 * 128 + lane;
            am  += a.x * wm[kb] + a.y * wm[kb + 32] + a.z * wm[kb + 64] + a.w * wm[kb + 96];
            as2 += b.x * ws2s[kb] + b.y * ws2s[kb + 32] + b.z * ws2s[kb + 64] + b.w * ws2s[kb + 96];
        }
        float mu = tanhf(am + bm[lane]);
        float sv = as2 + bs[lane];
        float sd = fmaxf(sv, 0.f) + log1pf(expf(-fabsf(sv)));
        float a_ = act[(size_t)r * ADV + lane];
        float z = (a_ - mu) / sd;
        ilacc += 0.5f * z * z + logf(sd) + 0.91893853320467274f;
    }
#pragma unroll
    for (int o = 16; o; o >>= 1) ilacc += __shfl_xor_sync(0xffffffffu, ilacc, o);
    if (lane == 0) red[w] = ilacc;
    __syncthreads();
    if (tid == 0) {
        float t = 0.f;
        for (int i = 0; i < 8; i++) t += red[i];
        pil[blockIdx.x] = t;
    }
}

// ---------------- final scalar reduce ----------------
__global__ void final_reduce_kernel(const float* __restrict__ pfl, const float* __restrict__ pil,
                                    float* __restrict__ out)
{
    __shared__ float s1[256], s2[256];
    int tid = threadIdx.x;
    float a = 0.f, b = 0.f;
    for (int i = tid; i < 2048; i += 256) a += pfl[i];
    for (int i = tid; i < 512; i += 256) b += pil[i];
    s1[tid] = a; s2[tid] = b;
    __syncthreads();
    for (int st = 128; st; st >>= 1) {
        if (tid < st) { s1[tid] += s1[tid + st]; s2[tid] += s2[tid + st]; }
        __syncthreads();
    }
    if (tid == 0) {
        out[0] = s1[0] / 33554432.f;
        out[1] = s2[0] / 4194304.f;
    }
}

// ---------------- host orchestration ----------------
extern "C" void kernel_launch(void* const* d_in, const int* in_sizes, int n_in,
                              void* d_out, int out_size)
{
    (void)in_sizes; (void)n_in; (void)out_size;
    const float* states = (const float*)d_in[0];
    const float* action = (const float*)d_in[1];
    const int*   dones  = (const int*)d_in[2];
    const float* Wfe = (const float*)d_in[3];
    const float* bfe = (const float*)d_in[4];
    const float* Wih0 = (const float*)d_in[5];
    const float* Whh0 = (const float*)d_in[6];
    const float* bih0 = (const float*)d_in[7];
    const float* bhh0 = (const float*)d_in[8];
    const float* Wih1 = (const float*)d_in[9];
    const float* Whh1 = (const float*)d_in[10];
    const float* bih1 = (const float*)d_in[11];
    const float* bhh1 = (const float*)d_in[12];
    const float* Wf1 = (const float*)d_in[13];
    const float* bf1 = (const float*)d_in[14];
    const float* Wf2 = (const float*)d_in[15];
    const float* bf2 = (const float*)d_in[16];
    const float* Wm1 = (const float*)d_in[17];
    const float* bm1 = (const float*)d_in[18];
    const float* Wm2 = (const float*)d_in[19];
    const float* bm2 = (const float*)d_in[20];
    const float* Ws1 = (const float*)d_in[21];
    const float* bs1 = (const float*)d_in[22];
    const float* Ws2 = (const float*)d_in[23];
    const float* bs2 = (const float*)d_in[24];
    float* out = (float*)d_out;

    float *feats, *xw, *outs, *h0hist, *pred, *hidA, *hidB, *c0, *c1, *pfl, *pil;
    cudaGetSymbolAddress((void**)&feats, g_feats);
    cudaGetSymbolAddress((void**)&xw, g_xw);
    cudaGetSymbolAddress((void**)&outs, g_outs);
    cudaGetSymbolAddress((void**)&h0hist, g_h0hist);
    cudaGetSymbolAddress((void**)&pred, g_pred);
    cudaGetSymbolAddress((void**)&hidA, g_hidA);
    cudaGetSymbolAddress((void**)&hidB, g_hidB);
    cudaGetSymbolAddress((void**)&c0, g_c0);
    cudaGetSymbolAddress((void**)&c1, g_c1);
    cudaGetSymbolAddress((void**)&pfl, g_pfl);
    cudaGetSymbolAddress((void**)&pil, g_pil);

    cudaFuncSetAttribute(inv_kernel, cudaFuncAttributeMaxDynamicSharedMemorySize, 32840 * 4);

    // init recurrent state (c0, c1, h0hist slot 0 = zeros)
    init_kernel<<<256, 512>>>();

    // feature encoder: feats = relu(states @ Wfe^T + bfe)
    gemm_kernel<1><<<dim3(RALL / 128, HSV / 128), 256>>>(
        states, SDV, nullptr, Wfe, bfe, feats, RALL, HSV, SDV);

    // hoisted layer-0 input gates: xw = feats @ Wih0^T + bih0
    gemm_kernel<0><<<dim3(RALL / 128, 1024 / 128), 256>>>(
        feats, HSV, nullptr, Wih0, bih0, xw, RALL, 1024, HSV);

    // LSTM scan: ONE fused launch per pipeline stage; L0(i) overlaps L1(i-1)
    float* hid = out + 2 + 131072;
    for (int i = 0; i <= 257; i++) {
        int s0 = (i <= 256) ? i : -1;
        int s1 = i - 1;
        lstm_fused<<<384, 256>>>(s0, s1, h0hist, xw, outs, c0, c1,
            Whh0, bhh0, Wih1, Whh1, bih1, bhh1, dones, hid);
    }

    // forward model
    gemm_kernel<1><<<dim3(R2 / 128, HSV / 128), 256>>>(
        outs, SFV, action, Wf1, bf1, hidA, R2, HSV, SFV + ADV);
    gemm_kernel<0><<<dim3(R2 / 128, SFV / 128), 256>>>(
        hidA, HSV, nullptr, Wf2, bf2, pred, R2, SFV, HSV);

    // forward loss + intrinsic reward
    floss_kernel<<<2048, 256>>>(pred, outs, out + 2, pfl);

    // inverse model hiddens
    gemm_kernel<1><<<dim3(R2 / 128, HSV / 128), 256>>>(
        outs, SFV, pred, Wm1, bm1, hidA, R2, HSV, 2 * SFV);
    gemm_kernel<1><<<dim3(R2 / 128, HSV / 128), 256>>>(
        outs, SFV, pred, Ws1, bs1, hidB, R2, HSV, 2 * SFV);

    // mu/std + inverse-loss partials
    inv_kernel<<<512, 256, 32840 * 4>>>(hidA, hidB, Wm2, bm2, Ws2, bs2, action, pil);

    // scalars
    final_reduce_kernel<<<1, 256>>>(pfl, pil, out);
}

// round 11
// speedup vs baseline: 1.4606x; 1.4606x over previous
#include <cuda_runtime.h>
#include <math.h>

#define T1V 257
#define BATCH 512
#define SDV 128
#define ADV 32
#define HSV 512
#define SFV 256
#define R2 131072    // 256*512 rows
#define RALL 131584  // 257*512 rows
#define WMAX 48      // max waves per layer (P(insufficient) ~1e-9 for Bernoulli(0.5) dones)

// ---------------- scratch (__device__ globals; no runtime allocation) ----------------
__device__ float g_feats[(size_t)T1V * BATCH * HSV];   // 257x512x512
__device__ float g_xw   [(size_t)RALL * 1024];         // xw0 then reused as xw1
__device__ float g_H0   [(size_t)RALL * SFV];          // h0(t,b) at row t*512+b
__device__ float g_outs [(size_t)RALL * SFV];          // h1(t,b) == outs
__device__ float g_C0   [(size_t)RALL * SFV];
__device__ float g_C1   [(size_t)RALL * SFV];
__device__ float g_pred [(size_t)R2 * SFV];
__device__ float g_hidA [(size_t)R2 * HSV];
__device__ float g_hidB [(size_t)R2 * HSV];
__device__ float g_pfl  [2048];
__device__ float g_pil  [512];
__device__ int   g_off  [RALL];
__device__ int   g_cnt  [260];
__device__ int   g_base [260];
__device__ int   g_cur  [260];
__device__ int   g_idx  [RALL];

__device__ __forceinline__ float sigmoidf_(float x) { return 1.0f / (1.0f + expf(-x)); }

// ---------------- bucketing: offset(t,b) and wave index lists ----------------
__global__ void bucket_count(const int* __restrict__ dones) {
    int b = threadIdx.x;           // 512 threads, 1 block
    if (b < 260) g_cnt[b] = 0;
    __syncthreads();
    int off = 0;
    for (int t = 0; t < T1V; t++) {
        int r = t * BATCH + b;
        if (t == 0 || dones[r]) off = 0; else off++;
        g_off[r] = off;
        atomicAdd(&g_cnt[off], 1);
    }
}

__global__ void bucket_scan() {
    if (threadIdx.x == 0) {
        int s = 0;
        for (int k = 0; k < 258; k++) { g_base[k] = s; g_cur[k] = s; s += g_cnt[k]; }
    }
}

__global__ void bucket_fill() {
    int r = blockIdx.x * 512 + threadIdx.x;   // grid 257 x 512 = RALL
    int k = g_off[r];
    int p = atomicAdd(&g_cur[k], 1);
    g_idx[p] = r;
}

// ---------------- wave 0: offset==0 rows, h_in = c_in = 0 -> elementwise on xw ----------------
__global__ void lstm_wave0(float* __restrict__ H, float* __restrict__ C,
                           const float* __restrict__ xw, const float* __restrict__ bhh) {
    const int cnt0 = g_cnt[0];
    const int u = threadIdx.x;     // 256 units
    for (int m = blockIdx.x; m < cnt0; m += gridDim.x) {
        int r = g_idx[m];          // base[0] == 0
        const float* x = xw + (size_t)r * 1024 + u;
        float pi = x[0]   + bhh[u];
        float pg = x[512] + bhh[512 + u];
        float po = x[768] + bhh[768 + u];
        float c2 = sigmoidf_(pi) * tanhf(pg);
        float h2 = sigmoidf_(po) * tanhf(c2);
        C[(size_t)r * SFV + u] = c2;
        H[(size_t)r * SFV + u] = h2;
    }
}

// ---------------- wave k>=1: gather-GEMM over bucket rows ----------------
// Tile 64 rows x 32 units (128 gatecols), 256 threads, microtile 4 rows x 2 units x 4 gates.
// gates = h_prev(row r-512) @ Whh^T + xw[r] + bhh; then cell update with c_prev(r-512).
__global__ __launch_bounds__(256) void lstm_wave(
    int k,
    float* __restrict__ H, float* __restrict__ C,
    const float* __restrict__ xw,
    const float* __restrict__ Whh, const float* __restrict__ bhh)
{
    const int count = g_cnt[k];
    const int m0 = blockIdx.x * 64;
    if (m0 >= count) return;
    const int* myidx = g_idx + g_base[k];
    const int u0 = blockIdx.y * 32;

    __shared__ float as_[16][68];
    __shared__ float ws_[16][132];
    __shared__ int ridx[64];

    const int tid = threadIdx.x;
    if (tid < 64) {
        int m = m0 + tid;
        ridx[tid] = myidx[m < count ? m : count - 1];
    }
    __syncthreads();

    const int mi = tid >> 4, ni = tid & 15;
    const int lrow = tid >> 2, lk = (tid & 3) * 4;   // A staging: row lrow, k-offset lk
    const int wc = tid >> 1, wk = (tid & 1) * 8;     // W staging: gatecol wc (= unit_local*4+gate)
    const int wunit = wc >> 2, wgate = wc & 3;
    const float* Wr = Whh + (size_t)((wgate << 8) + u0 + wunit) * SFV;
    const float* Ar = H + (size_t)(ridx[lrow] - BATCH) * SFV;

    float acc[4][8];
#pragma unroll
    for (int i = 0; i < 4; i++)
#pragma unroll
        for (int j = 0; j < 8; j++) acc[i][j] = 0.f;

    for (int kc = 0; kc < SFV; kc += 16) {
        float4 av = *(const float4*)(Ar + kc + lk);
        float4 w0 = *(const float4*)(Wr + kc + wk);
        float4 w1 = *(const float4*)(Wr + kc + wk + 4);
        as_[lk + 0][lrow] = av.x; as_[lk + 1][lrow] = av.y;
        as_[lk + 2][lrow] = av.z; as_[lk + 3][lrow] = av.w;
        ws_[wk + 0][wc] = w0.x; ws_[wk + 1][wc] = w0.y;
        ws_[wk + 2][wc] = w0.z; ws_[wk + 3][wc] = w0.w;
        ws_[wk + 4][wc] = w1.x; ws_[wk + 5][wc] = w1.y;
        ws_[wk + 6][wc] = w1.z; ws_[wk + 7][wc] = w1.w;
        __syncthreads();
#pragma unroll
        for (int kk = 0; kk < 16; kk++) {
            float4 a4 = *(const float4*)&as_[kk][mi << 2];
            float4 wa = *(const float4*)&ws_[kk][ni << 2];          // unit ni, gates 0..3
            float4 wb = *(const float4*)&ws_[kk][(16 + ni) << 2];   // unit ni+16, gates 0..3
            float aa[4] = {a4.x, a4.y, a4.z, a4.w};
#pragma unroll
            for (int i = 0; i < 4; i++) {
                acc[i][0] += aa[i] * wa.x; acc[i][1] += aa[i] * wa.y;
                acc[i][2] += aa[i] * wa.z; acc[i][3] += aa[i] * wa.w;
                acc[i][4] += aa[i] * wb.x; acc[i][5] += aa[i] * wb.y;
                acc[i][6] += aa[i] * wb.z; acc[i][7] += aa[i] * wb.w;
            }
        }
        __syncthreads();
    }

    // epilogue
#pragma unroll
    for (int i = 0; i < 4; i++) {
        const int m = m0 + (mi << 2) + i;
        if (m >= count) continue;
        const int r = ridx[(mi << 2) + i];
        const float* xr = xw + (size_t)r * 1024;
        const float* cp = C + (size_t)(r - BATCH) * SFV;
#pragma unroll
        for (int u2 = 0; u2 < 2; u2++) {
            const int u = u0 + ni + (u2 << 4);
            const int j0 = u2 << 2;
            float pi = acc[i][j0 + 0] + xr[u]       + bhh[u];
            float pf = acc[i][j0 + 1] + xr[256 + u] + bhh[256 + u];
            float pg = acc[i][j0 + 2] + xr[512 + u] + bhh[512 + u];
            float po = acc[i][j0 + 3] + xr[768 + u] + bhh[768 + u];
            float c2 = sigmoidf_(pf) * cp[u] + sigmoidf_(pi) * tanhf(pg);
            float h2 = sigmoidf_(po) * tanhf(c2);
            C[(size_t)r * SFV + u] = c2;
            H[(size_t)r * SFV + u] = h2;
        }
    }
}

// ---------------- generic SGEMM: C = act(A @ W^T + bias) ----------------
#define KC 16
template <int ACT>
__global__ __launch_bounds__(256) void gemm_kernel(
    const float* __restrict__ A1, int K1,
    const float* __restrict__ A2,
    const float* __restrict__ W,
    const float* __restrict__ bias,
    float* __restrict__ C,
    int M, int N, int K)
{
    __shared__ float as_[KC][132];
    __shared__ float bs_[KC][132];
    const int m0 = blockIdx.x * 128;
    const int n0 = blockIdx.y * 128;
    const int tid = threadIdx.x;
    const int mi = tid >> 4;
    const int ni = tid & 15;
    const int lrow = tid >> 2;
    const int lk = (tid & 3) * 4;

    float acc[8][8];
#pragma unroll
    for (int i = 0; i < 8; i++)
#pragma unroll
        for (int j = 0; j < 8; j++) acc[i][j] = 0.f;

    for (int kc = 0; kc < K; kc += KC) {
        const float* Asrc;
        int Ak, koff;
        if (kc < K1) { Asrc = A1; Ak = K1; koff = kc; }
        else         { Asrc = A2; Ak = K - K1; koff = kc - K1; }
#pragma unroll
        for (int r = 0; r < 2; r++) {
            int row = lrow + r * 64;
            float4 v = *(const float4*)(Asrc + (size_t)(m0 + row) * Ak + koff + lk);
            as_[lk + 0][row] = v.x; as_[lk + 1][row] = v.y;
            as_[lk + 2][row] = v.z; as_[lk + 3][row] = v.w;
            float4 w = *(const float4*)(W + (size_t)(n0 + row) * K + kc + lk);
            bs_[lk + 0][row] = w.x; bs_[lk + 1][row] = w.y;
            bs_[lk + 2][row] = w.z; bs_[lk + 3][row] = w.w;
        }
        __syncthreads();
#pragma unroll
        for (int k = 0; k < KC; k++) {
            float4 a0 = *(const float4*)&as_[k][mi * 8];
            float4 a1 = *(const float4*)&as_[k][mi * 8 + 4];
            float a[8] = {a0.x, a0.y, a0.z, a0.w, a1.x, a1.y, a1.z, a1.w};
            float b[8];
#pragma unroll
            for (int j = 0; j < 8; j++) b[j] = bs_[k][ni + j * 16];
#pragma unroll
            for (int i = 0; i < 8; i++)
#pragma unroll
                for (int j = 0; j < 8; j++) acc[i][j] += a[i] * b[j];
        }
        __syncthreads();
    }
#pragma unroll
    for (int i = 0; i < 8; i++) {
        int row = m0 + mi * 8 + i;
#pragma unroll
        for (int j = 0; j < 8; j++) {
            int col = n0 + ni + j * 16;
            float v = acc[i][j] + bias[col];
            if (ACT == 1) v = fmaxf(v, 0.f);
            C[(size_t)row * N + col] = v;
        }
    }
}

// ---------------- forward loss + intrinsic reward ----------------
__global__ void floss_kernel(const float* __restrict__ pred, const float* __restrict__ outs,
                             float* __restrict__ intr, float* __restrict__ pfl)
{
    const int w = threadIdx.x >> 5, lane = threadIdx.x & 31;
    const int r0 = blockIdx.x * 64;
    __shared__ float sred[8];
    float wacc = 0.f;
    for (int p = 0; p < 8; p++) {
        int r = r0 + p * 8 + w;
        const float4* pp = (const float4*)(pred + (size_t)r * SFV) + lane * 2;
        const float4* np = (const float4*)(outs + (size_t)(r + BATCH) * SFV) + lane * 2;
        float4 p0 = pp[0], p1 = pp[1], n0 = np[0], n1 = np[1];
        float d0 = p0.x - n0.x, d1 = p0.y - n0.y, d2 = p0.z - n0.z, d3 = p0.w - n0.w;
        float d4 = p1.x - n1.x, d5 = p1.y - n1.y, d6 = p1.z - n1.z, d7 = p1.w - n1.w;
        float s = d0 * d0 + d1 * d1 + d2 * d2 + d3 * d3 + d4 * d4 + d5 * d5 + d6 * d6 + d7 * d7;
#pragma unroll
        for (int o = 16; o; o >>= 1) s += __shfl_xor_sync(0xffffffffu, s, o);
        if (lane == 0) { intr[r] = s; wacc += s; }
    }
    if (lane == 0) sred[w] = wacc;
    __syncthreads();
    if (threadIdx.x == 0) {
        float t = 0.f;
        for (int i = 0; i < 8; i++) t += sred[i];
        pfl[blockIdx.x] = t;
    }
}

// ---------------- inverse head: mu/std + NLL partials ----------------
__global__ void inv_kernel(const float* __restrict__ hm, const float* __restrict__ hs,
                           const float* __restrict__ Wm2, const float* __restrict__ bm2,
                           const float* __restrict__ Ws2, const float* __restrict__ bs2,
                           const float* __restrict__ act, float* __restrict__ pil)
{
    extern __shared__ float sh[];
    float* wm = sh;
    float* ws2s = sh + 16384;
    float* bm = sh + 32768;
    float* bs = sh + 32800;
    float* red = sh + 32832;
    const int tid = threadIdx.x;
    for (int idx = tid; idx < 16384; idx += 256) {
        int d = idx & 31, k = idx >> 5;
        wm[idx] = Wm2[(size_t)d * HSV + k];
        ws2s[idx] = Ws2[(size_t)d * HSV + k];
    }
    if (tid < 32) { bm[tid] = bm2[tid]; bs[tid] = bs2[tid]; }
    __syncthreads();

    const int w = tid >> 5, lane = tid & 31;
    const int r0 = blockIdx.x * 256;
    float ilacc = 0.f;
    for (int p = 0; p < 32; p++) {
        int r = r0 + p * 8 + w;
        const float4* h4m = (const float4*)(hm + (size_t)r * HSV);
        const float4* h4s = (const float4*)(hs + (size_t)r * HSV);
        float am = 0.f, as2 = 0.f;
#pragma unroll 4
        for (int k4 = 0; k4 < 128; k4++) {
            float4 a = h4m[k4];
            float4 b = h4s[k4];
            int kb = k4 * 128 + lane;
            am  += a.x * wm[kb] + a.y * wm[kb + 32] + a.z * wm[kb + 64] + a.w * wm[kb + 96];
            as2 += b.x * ws2s[kb] + b.y * ws2s[kb + 32] + b.z * ws2s[kb + 64] + b.w * ws2s[kb + 96];
        }
        float mu = tanhf(am + bm[lane]);
        float sv = as2 + bs[lane];
        float sd = fmaxf(sv, 0.f) + log1pf(expf(-fabsf(sv)));
        float a_ = act[(size_t)r * ADV + lane];
        float z = (a_ - mu) / sd;
        ilacc += 0.5f * z * z + logf(sd) + 0.91893853320467274f;
    }
#pragma unroll
    for (int o = 16; o; o >>= 1) ilacc += __shfl_xor_sync(0xffffffffu, ilacc, o);
    if (lane == 0) red[w] = ilacc;
    __syncthreads();
    if (tid == 0) {
        float t = 0.f;
        for (int i = 0; i < 8; i++) t += red[i];
        pil[blockIdx.x] = t;
    }
}

// ---------------- final scalar reduce ----------------
__global__ void final_reduce_kernel(const float* __restrict__ pfl, const float* __restrict__ pil,
                                    float* __restrict__ out)
{
    __shared__ float s1[256], s2[256];
    int tid = threadIdx.x;
    float a = 0.f, b = 0.f;
    for (int i = tid; i < 2048; i += 256) a += pfl[i];
    for (int i = tid; i < 512; i += 256) b += pil[i];
    s1[tid] = a; s2[tid] = b;
    __syncthreads();
    for (int st = 128; st; st >>= 1) {
        if (tid < st) { s1[tid] += s1[tid + st]; s2[tid] += s2[tid + st]; }
        __syncthreads();
    }
    if (tid == 0) {
        out[0] = s1[0] / 33554432.f;
        out[1] = s2[0] / 4194304.f;
    }
}

// ---------------- hidden copy ----------------
__global__ void hid_copy(const float* __restrict__ H0, const float* __restrict__ H1,
                         const float* __restrict__ C0, const float* __restrict__ C1,
                         float* __restrict__ hid)
{
    int i = blockIdx.x * blockDim.x + threadIdx.x;  // 131072
    const size_t o = (size_t)131072 * 256 + i;       // rows t=256
    hid[i]          = H0[o];
    hid[131072 + i] = H1[o];
    hid[262144 + i] = C0[o];
    hid[393216 + i] = C1[o];
}

// ---------------- host orchestration ----------------
extern "C" void kernel_launch(void* const* d_in, const int* in_sizes, int n_in,
                              void* d_out, int out_size)
{
    (void)in_sizes; (void)n_in; (void)out_size;
    const float* states = (const float*)d_in[0];
    const float* action = (const float*)d_in[1];
    const int*   dones  = (const int*)d_in[2];
    const float* Wfe = (const float*)d_in[3];
    const float* bfe = (const float*)d_in[4];
    const float* Wih0 = (const float*)d_in[5];
    const float* Whh0 = (const float*)d_in[6];
    const float* bih0 = (const float*)d_in[7];
    const float* bhh0 = (const float*)d_in[8];
    const float* Wih1 = (const float*)d_in[9];
    const float* Whh1 = (const float*)d_in[10];
    const float* bih1 = (const float*)d_in[11];
    const float* bhh1 = (const float*)d_in[12];
    const float* Wf1 = (const float*)d_in[13];
    const float* bf1 = (const float*)d_in[14];
    const float* Wf2 = (const float*)d_in[15];
    const float* bf2 = (const float*)d_in[16];
    const float* Wm1 = (const float*)d_in[17];
    const float* bm1 = (const float*)d_in[18];
    const float* Wm2 = (const float*)d_in[19];
    const float* bm2 = (const float*)d_in[20];
    const float* Ws1 = (const float*)d_in[21];
    const float* bs1 = (const float*)d_in[22];
    const float* Ws2 = (const float*)d_in[23];
    const float* bs2 = (const float*)d_in[24];
    float* out = (float*)d_out;

    float *feats, *xw, *H0, *H1, *C0, *C1, *pred, *hidA, *hidB, *pfl, *pil;
    cudaGetSymbolAddress((void**)&feats, g_feats);
    cudaGetSymbolAddress((void**)&xw, g_xw);
    cudaGetSymbolAddress((void**)&H0, g_H0);
    cudaGetSymbolAddress((void**)&H1, g_outs);
    cudaGetSymbolAddress((void**)&C0, g_C0);
    cudaGetSymbolAddress((void**)&C1, g_C1);
    cudaGetSymbolAddress((void**)&pred, g_pred);
    cudaGetSymbolAddress((void**)&hidA, g_hidA);
    cudaGetSymbolAddress((void**)&hidB, g_hidB);
    cudaGetSymbolAddress((void**)&pfl, g_pfl);
    cudaGetSymbolAddress((void**)&pil, g_pil);

    cudaFuncSetAttribute(inv_kernel, cudaFuncAttributeMaxDynamicSharedMemorySize, 32840 * 4);

    // bucketing (offset per row, wave index lists)
    bucket_count<<<1, 512>>>(dones);
    bucket_scan<<<1, 32>>>();
    bucket_fill<<<257, 512>>>();

    // feature encoder: feats = relu(states @ Wfe^T + bfe)
    gemm_kernel<1><<<dim3(RALL / 128, HSV / 128), 256>>>(
        states, SDV, nullptr, Wfe, bfe, feats, RALL, HSV, SDV);

    // xw0 = feats @ Wih0^T + bih0 (all steps)
    gemm_kernel<0><<<dim3(RALL / 128, 1024 / 128), 256>>>(
        feats, HSV, nullptr, Wih0, bih0, xw, RALL, 1024, HSV);

    // -------- layer 0 by waves --------
    lstm_wave0<<<512, 256>>>(H0, C0, xw, bhh0);
    for (int k = 1; k < WMAX; k++) {
        int bound = RALL / (k + 1);              // count_k <= RALL/(k+1)
        int gx = (bound + 63) / 64;
        lstm_wave<<<dim3(gx, 8), 256>>>(k, H0, C0, xw, Whh0, bhh0);
    }

    // xw1 = H0 @ Wih1^T + bih1 (reuse xw buffer; stream-ordered after L0 waves)
    gemm_kernel<0><<<dim3(RALL / 128, 1024 / 128), 256>>>(
        H0, SFV, nullptr, Wih1, bih1, xw, RALL, 1024, SFV);

    // -------- layer 1 by waves --------
    lstm_wave0<<<512, 256>>>(H1, C1, xw, bhh1);
    for (int k = 1; k < WMAX; k++) {
        int bound = RALL / (k + 1);
        int gx = (bound + 63) / 64;
        lstm_wave<<<dim3(gx, 8), 256>>>(k, H1, C1, xw, Whh1, bhh1);
    }

    // forward model
    gemm_kernel<1><<<dim3(R2 / 128, HSV / 128), 256>>>(
        H1, SFV, action, Wf1, bf1, hidA, R2, HSV, SFV + ADV);
    gemm_kernel<0><<<dim3(R2 / 128, SFV / 128), 256>>>(
        hidA, HSV, nullptr, Wf2, bf2, pred, R2, SFV, HSV);

    // forward loss + intrinsic reward
    floss_kernel<<<2048, 256>>>(pred, H1, out + 2, pfl);

    // inverse model hiddens
    gemm_kernel<1><<<dim3(R2 / 128, HSV / 128), 256>>>(
        H1, SFV, pred, Wm1, bm1, hidA, R2, HSV, 2 * SFV);
    gemm_kernel<1><<<dim3(R2 / 128, HSV / 128), 256>>>(
        H1, SFV, pred, Ws1, bs1, hidB, R2, HSV, 2 * SFV);

    // mu/std + inverse-loss partials
    inv_kernel<<<512, 256, 32840 * 4>>>(hidA, hidB, Wm2, bm2, Ws2, bs2, action, pil);

    // scalars
    final_reduce_kernel<<<1, 256>>>(pfl, pil, out);

    // hidden = [h0_T, h1_T, c0_T, c1_T]
    hid_copy<<<256, 512>>>(H0, H1, C0, C1, out + 2 + 131072);
}

// round 12
// speedup vs baseline: 1.4692x; 1.0059x over previous
#include <cuda_runtime.h>
#include <math.h>

#define T1V 257
#define BATCH 512
#define SDV 128
#define ADV 32
#define HSV 512
#define SFV 256
#define R2 131072    // 256*512 rows
#define RALL 131584  // 257*512 rows
#define MAXTILES 4096
#define DAGGRID 1024

// ---------------- scratch (__device__ globals; no runtime allocation) ----------------
__device__ float g_feats[(size_t)T1V * BATCH * HSV];   // 257x512x512
__device__ float g_xw   [(size_t)RALL * 1024];         // xw0 then reused as xw1
__device__ float g_H0   [(size_t)RALL * SFV];          // h0(t,b) at row t*512+b
__device__ float g_outs [(size_t)RALL * SFV];          // h1(t,b) == outs
__device__ float g_C0   [(size_t)RALL * SFV];
__device__ float g_C1   [(size_t)RALL * SFV];
__device__ float g_pred [(size_t)R2 * SFV];
__device__ float g_hidA [(size_t)R2 * HSV];
__device__ float g_hidB [(size_t)R2 * HSV];
__device__ float g_pfl  [2048];
__device__ float g_pil  [512];
__device__ int   g_off  [RALL];
__device__ int   g_cnt  [260];
__device__ int   g_base [260];
__device__ int   g_cur  [260];
__device__ int   g_idx  [RALL];
__device__ int   g_rowtile [RALL];
__device__ int   g_tilebase[260];
__device__ int   g_tiledesc[MAXTILES];   // start position in g_idx
__device__ int   g_tilerows[MAXTILES];   // rows in tile (1..64)
__device__ int   g_ntile;
__device__ int   g_qh[2];
__device__ int   g_tilecnt [2 * MAXTILES];
__device__ int   g_tiledone[2 * MAXTILES];

__device__ __forceinline__ float sigmoidf_(float x) { return 1.0f / (1.0f + expf(-x)); }

// ---------------- init: zero queue/flags ----------------
__global__ void init_kernel() {
    int i = blockIdx.x * blockDim.x + threadIdx.x;   // 32 x 512 = 16384 >= 2*MAXTILES
    if (i < 2 * MAXTILES) { g_tilecnt[i] = 0; g_tiledone[i] = 0; }
    if (i < 2) g_qh[i] = 0;
}

// ---------------- bucketing ----------------
__global__ void bucket_count(const int* __restrict__ dones) {
    __shared__ int sc[260];
    int b = threadIdx.x;           // 512 threads, 1 block
    if (b < 260) sc[b] = 0;
    __syncthreads();
    int off = 0;
    for (int t = 0; t < T1V; t++) {
        int r = t * BATCH + b;
        if (t == 0 || dones[r]) off = 0; else off++;
        g_off[r] = off;
        atomicAdd(&sc[off], 1);
    }
    __syncthreads();
    if (b < 260) g_cnt[b] = sc[b];
}

__global__ void bucket_scan() {
    if (threadIdx.x == 0) {
        int s = 0, tb = 0;
        for (int k = 0; k < 258; k++) {
            g_base[k] = s; g_cur[k] = s; s += g_cnt[k];
            g_tilebase[k] = tb;
            if (k > 0) tb += (g_cnt[k] + 63) >> 6;
        }
        g_ntile = tb;
    }
}

__global__ void bucket_fill() {
    int r = blockIdx.x * 512 + threadIdx.x;   // grid 257 x 512 = RALL
    int k = g_off[r];
    int p = atomicAdd(&g_cur[k], 1);
    g_idx[p] = r;
}

__global__ void rowtile_init() {
    int r = blockIdx.x * 512 + threadIdx.x;
    g_rowtile[r] = -1;
}

// grid 258 blocks (one per wave k), 256 threads
__global__ void tile_fill() {
    int k = blockIdx.x;
    if (k == 0) return;
    int cnt = g_cnt[k];
    if (cnt == 0) return;
    int tb = g_tilebase[k];
    int base = g_base[k];
    int ntk = (cnt + 63) >> 6;
    for (int j = threadIdx.x; j < ntk; j += 256) {
        g_tiledesc[tb + j] = base + (j << 6);
        int rem = cnt - (j << 6);
        g_tilerows[tb + j] = rem < 64 ? rem : 64;
    }
    for (int p = threadIdx.x; p < cnt; p += 256)
        g_rowtile[g_idx[base + p]] = tb + (p >> 6);
}

// ---------------- wave 0: h_in = c_in = 0 -> elementwise on xw ----------------
__global__ void lstm_wave0(float* __restrict__ H, float* __restrict__ C,
                           const float* __restrict__ xw, const float* __restrict__ bhh) {
    const int cnt0 = g_cnt[0];
    const int u = threadIdx.x;     // 256 units
    for (int m = blockIdx.x; m < cnt0; m += gridDim.x) {
        int r = g_idx[m];          // base[0] == 0
        const float* x = xw + (size_t)r * 1024 + u;
        float pi = x[0]   + bhh[u];
        float pg = x[512] + bhh[512 + u];
        float po = x[768] + bhh[768 + u];
        float c2 = sigmoidf_(pi) * tanhf(pg);
        float h2 = sigmoidf_(po) * tanhf(c2);
        C[(size_t)r * SFV + u] = c2;
        H[(size_t)r * SFV + u] = h2;
    }
}

// ---------------- DAG executor: all waves k>=1 of one layer in ONE launch ----------
// Work-queue of entries e = tile*8 + y (y = 32-unit group). Tiles listed in wave-
// ascending order; per-tile done-flags gate consumers. Deadlock-free: minimal
// in-flight entry always has all predecessor tiles finished.
__global__ __launch_bounds__(256) void lstm_dag(
    int layer,
    float* __restrict__ H, float* __restrict__ C,
    const float* __restrict__ xw,
    const float* __restrict__ Whh, const float* __restrict__ bhh)
{
    __shared__ float as_[16][68];
    __shared__ float ws_[16][132];
    __shared__ int ridx[64];
    __shared__ int sh_e;

    const int tid = threadIdx.x;
    const int nent = g_ntile * 8;
    int* qh = &g_qh[layer];
    int* tcnt = g_tilecnt + layer * MAXTILES;
    volatile int* tdone = (volatile int*)(g_tiledone + layer * MAXTILES);

    const int mi = tid >> 4, ni = tid & 15;
    const int lrow = tid >> 2, lk = (tid & 3) * 4;
    const int wc = tid >> 1, wk = (tid & 1) * 8;
    const int wunit = wc >> 2, wgate = wc & 3;

    while (true) {
        __syncthreads();
        if (tid == 0) sh_e = atomicAdd(qh, 1);
        __syncthreads();
        const int e = sh_e;
        if (e >= nent) break;
        const int tile = e >> 3;
        const int u0 = (e & 7) << 5;
        const int start = g_tiledesc[tile];
        const int rows = g_tilerows[tile];

        if (tid < 64) {
            int m = tid < rows ? tid : 0;
            ridx[tid] = g_idx[start + m];
        }
        __syncthreads();

        // wait for predecessor tiles (pred row = r - 512; wave-0 preds are done pre-launch)
        if (tid < 64) {
            int pt = g_rowtile[ridx[tid] - BATCH];
            if (pt >= 0) {
                while (tdone[pt] == 0) __nanosleep(64);
            }
        }
        __threadfence();
        __syncthreads();

        const float* Wr = Whh + (size_t)((wgate << 8) + u0 + wunit) * SFV;
        const float* Ar = H + (size_t)(ridx[lrow] - BATCH) * SFV;

        float acc[4][8];
#pragma unroll
        for (int i = 0; i < 4; i++)
#pragma unroll
            for (int j = 0; j < 8; j++) acc[i][j] = 0.f;

        for (int kc = 0; kc < SFV; kc += 16) {
            float4 av = *(const float4*)(Ar + kc + lk);
            float4 w0 = *(const float4*)(Wr + kc + wk);
            float4 w1 = *(const float4*)(Wr + kc + wk + 4);
            as_[lk + 0][lrow] = av.x; as_[lk + 1][lrow] = av.y;
            as_[lk + 2][lrow] = av.z; as_[lk + 3][lrow] = av.w;
            ws_[wk + 0][wc] = w0.x; ws_[wk + 1][wc] = w0.y;
            ws_[wk + 2][wc] = w0.z; ws_[wk + 3][wc] = w0.w;
            ws_[wk + 4][wc] = w1.x; ws_[wk + 5][wc] = w1.y;
            ws_[wk + 6][wc] = w1.z; ws_[wk + 7][wc] = w1.w;
            __syncthreads();
#pragma unroll
            for (int kk = 0; kk < 16; kk++) {
                float4 a4 = *(const float4*)&as_[kk][mi << 2];
                float4 wa = *(const float4*)&ws_[kk][ni << 2];
                float4 wb = *(const float4*)&ws_[kk][(16 + ni) << 2];
                float aa[4] = {a4.x, a4.y, a4.z, a4.w};
#pragma unroll
                for (int i = 0; i < 4; i++) {
                    acc[i][0] += aa[i] * wa.x; acc[i][1] += aa[i] * wa.y;
                    acc[i][2] += aa[i] * wa.z; acc[i][3] += aa[i] * wa.w;
                    acc[i][4] += aa[i] * wb.x; acc[i][5] += aa[i] * wb.y;
                    acc[i][6] += aa[i] * wb.z; acc[i][7] += aa[i] * wb.w;
                }
            }
            __syncthreads();
        }

        // epilogue (duplicated padded rows write identical values - benign)
#pragma unroll
        for (int i = 0; i < 4; i++) {
            const int r = ridx[(mi << 2) + i];
            const float* xr = xw + (size_t)r * 1024;
            const float* cp = C + (size_t)(r - BATCH) * SFV;
#pragma unroll
            for (int u2 = 0; u2 < 2; u2++) {
                const int u = u0 + ni + (u2 << 4);
                const int j0 = u2 << 2;
                float pi = acc[i][j0 + 0] + xr[u]       + bhh[u];
                float pf = acc[i][j0 + 1] + xr[256 + u] + bhh[256 + u];
                float pg = acc[i][j0 + 2] + xr[512 + u] + bhh[512 + u];
                float po = acc[i][j0 + 3] + xr[768 + u] + bhh[768 + u];
                float c2 = sigmoidf_(pf) * cp[u] + sigmoidf_(pi) * tanhf(pg);
                float h2 = sigmoidf_(po) * tanhf(c2);
                C[(size_t)r * SFV + u] = c2;
                H[(size_t)r * SFV + u] = h2;
            }
        }

        __threadfence();
        __syncthreads();
        if (tid == 0) {
            int old = atomicAdd(&tcnt[tile], 1);
            if (old == 7) atomicExch((int*)&tdone[tile], 1);
        }
    }
}

// ---------------- generic SGEMM: C = act(A @ W^T + bias) ----------------
#define KC 16
template <int ACT>
__global__ __launch_bounds__(256) void gemm_kernel(
    const float* __restrict__ A1, int K1,
    const float* __restrict__ A2,
    const float* __restrict__ W,
    const float* __restrict__ bias,
    float* __restrict__ C,
    int M, int N, int K)
{
    __shared__ float as_[KC][132];
    __shared__ float bs_[KC][132];
    const int m0 = blockIdx.x * 128;
    const int n0 = blockIdx.y * 128;
    const int tid = threadIdx.x;
    const int mi = tid >> 4;
    const int ni = tid & 15;
    const int lrow = tid >> 2;
    const int lk = (tid & 3) * 4;

    float acc[8][8];
#pragma unroll
    for (int i = 0; i < 8; i++)
#pragma unroll
        for (int j = 0; j < 8; j++) acc[i][j] = 0.f;

    for (int kc = 0; kc < K; kc += KC) {
        const float* Asrc;
        int Ak, koff;
        if (kc < K1) { Asrc = A1; Ak = K1; koff = kc; }
        else         { Asrc = A2; Ak = K - K1; koff = kc - K1; }
#pragma unroll
        for (int r = 0; r < 2; r++) {
            int row = lrow + r * 64;
            float4 v = *(const float4*)(Asrc + (size_t)(m0 + row) * Ak + koff + lk);
            as_[lk + 0][row] = v.x; as_[lk + 1][row] = v.y;
            as_[lk + 2][row] = v.z; as_[lk + 3][row] = v.w;
            float4 w = *(const float4*)(W + (size_t)(n0 + row) * K + kc + lk);
            bs_[lk + 0][row] = w.x; bs_[lk + 1][row] = w.y;
            bs_[lk + 2][row] = w.z; bs_[lk + 3][row] = w.w;
        }
        __syncthreads();
#pragma unroll
        for (int k = 0; k < KC; k++) {
            float4 a0 = *(const float4*)&as_[k][mi * 8];
            float4 a1 = *(const float4*)&as_[k][mi * 8 + 4];
            float a[8] = {a0.x, a0.y, a0.z, a0.w, a1.x, a1.y, a1.z, a1.w};
            float b[8];
#pragma unroll
            for (int j = 0; j < 8; j++) b[j] = bs_[k][ni + j * 16];
#pragma unroll
            for (int i = 0; i < 8; i++)
#pragma unroll
                for (int j = 0; j < 8; j++) acc[i][j] += a[i] * b[j];
        }
        __syncthreads();
    }
#pragma unroll
    for (int i = 0; i < 8; i++) {
        int row = m0 + mi * 8 + i;
#pragma unroll
        for (int j = 0; j < 8; j++) {
            int col = n0 + ni + j * 16;
            float v = acc[i][j] + bias[col];
            if (ACT == 1) v = fmaxf(v, 0.f);
            C[(size_t)row * N + col] = v;
        }
    }
}

// ---------------- forward loss + intrinsic reward ----------------
__global__ void floss_kernel(const float* __restrict__ pred, const float* __restrict__ outs,
                             float* __restrict__ intr, float* __restrict__ pfl)
{
    const int w = threadIdx.x >> 5, lane = threadIdx.x & 31;
    const int r0 = blockIdx.x * 64;
    __shared__ float sred[8];
    float wacc = 0.f;
    for (int p = 0; p < 8; p++) {
        int r = r0 + p * 8 + w;
        const float4* pp = (const float4*)(pred + (size_t)r * SFV) + lane * 2;
        const float4* np = (const float4*)(outs + (size_t)(r + BATCH) * SFV) + lane * 2;
        float4 p0 = pp[0], p1 = pp[1], n0 = np[0], n1 = np[1];
        float d0 = p0.x - n0.x, d1 = p0.y - n0.y, d2 = p0.z - n0.z, d3 = p0.w - n0.w;
        float d4 = p1.x - n1.x, d5 = p1.y - n1.y, d6 = p1.z - n1.z, d7 = p1.w - n1.w;
        float s = d0 * d0 + d1 * d1 + d2 * d2 + d3 * d3 + d4 * d4 + d5 * d5 + d6 * d6 + d7 * d7;
#pragma unroll
        for (int o = 16; o; o >>= 1) s += __shfl_xor_sync(0xffffffffu, s, o);
        if (lane == 0) { intr[r] = s; wacc += s; }
    }
    if (lane == 0) sred[w] = wacc;
    __syncthreads();
    if (threadIdx.x == 0) {
        float t = 0.f;
        for (int i = 0; i < 8; i++) t += sred[i];
        pfl[blockIdx.x] = t;
    }
}

// ---------------- inverse head: mu/std + NLL partials ----------------
__global__ void inv_kernel(const float* __restrict__ hm, const float* __restrict__ hs,
                           const float* __restrict__ Wm2, const float* __restrict__ bm2,
                           const float* __restrict__ Ws2, const float* __restrict__ bs2,
                           const float* __restrict__ act, float* __restrict__ pil)
{
    extern __shared__ float sh[];
    float* wm = sh;
    float* ws2s = sh + 16384;
    float* bm = sh + 32768;
    float* bs = sh + 32800;
    float* red = sh + 32832;
    const int tid = threadIdx.x;
    for (int idx = tid; idx < 16384; idx += 256) {
        int d = idx & 31, k = idx >> 5;
        wm[idx] = Wm2[(size_t)d * HSV + k];
        ws2s[idx] = Ws2[(size_t)d * HSV + k];
    }
    if (tid < 32) { bm[tid] = bm2[tid]; bs[tid] = bs2[tid]; }
    __syncthreads();

    const int w = tid >> 5, lane = tid & 31;
    const int r0 = blockIdx.x * 256;
    float ilacc = 0.f;
    for (int p = 0; p < 32; p++) {
        int r = r0 + p * 8 + w;
        const float4* h4m = (const float4*)(hm + (size_t)r * HSV);
        const float4* h4s = (const float4*)(hs + (size_t)r * HSV);
        float am = 0.f, as2 = 0.f;
#pragma unroll 4
        for (int k4 = 0; k4 < 128; k4++) {
            float4 a = h4m[k4];
            float4 b = h4s[k4];
            int kb = k4 * 128 + lane;
            am  += a.x * wm[kb] + a.y * wm[kb + 32] + a.z * wm[kb + 64] + a.w * wm[kb + 96];
            as2 += b.x * ws2s[kb] + b.y * ws2s[kb + 32] + b.z * ws2s[kb + 64] + b.w * ws2s[kb + 96];
        }
        float mu = tanhf(am + bm[lane]);
        float sv = as2 + bs[lane];
        float sd = fmaxf(sv, 0.f) + log1pf(expf(-fabsf(sv)));
        float a_ = act[(size_t)r * ADV + lane];
        float z = (a_ - mu) / sd;
        ilacc += 0.5f * z * z + logf(sd) + 0.91893853320467274f;
    }
#pragma unroll
    for (int o = 16; o; o >>= 1) ilacc += __shfl_xor_sync(0xffffffffu, ilacc, o);
    if (lane == 0) red[w] = ilacc;
    __syncthreads();
    if (tid == 0) {
        float t = 0.f;
        for (int i = 0; i < 8; i++) t += red[i];
        pil[blockIdx.x] = t;
    }
}

// ---------------- final scalar reduce ----------------
__global__ void final_reduce_kernel(const float* __restrict__ pfl, const float* __restrict__ pil,
                                    float* __restrict__ out)
{
    __shared__ float s1[256], s2[256];
    int tid = threadIdx.x;
    float a = 0.f, b = 0.f;
    for (int i = tid; i < 2048; i += 256) a += pfl[i];
    for (int i = tid; i < 512; i += 256) b += pil[i];
    s1[tid] = a; s2[tid] = b;
    __syncthreads();
    for (int st = 128; st; st >>= 1) {
        if (tid < st) { s1[tid] += s1[tid + st]; s2[tid] += s2[tid + st]; }
        __syncthreads();
    }
    if (tid == 0) {
        out[0] = s1[0] / 33554432.f;
        out[1] = s2[0] / 4194304.f;
    }
}

// ---------------- hidden copy ----------------
__global__ void hid_copy(const float* __restrict__ H0, const float* __restrict__ H1,
                         const float* __restrict__ C0, const float* __restrict__ C1,
                         float* __restrict__ hid)
{
    int i = blockIdx.x * blockDim.x + threadIdx.x;  // 131072
    const size_t o = (size_t)131072 * 256 + i;       // rows t=256
    hid[i]          = H0[o];
    hid[131072 + i] = H1[o];
    hid[262144 + i] = C0[o];
    hid[393216 + i] = C1[o];
}

// ---------------- host orchestration ----------------
extern "C" void kernel_launch(void* const* d_in, const int* in_sizes, int n_in,
                              void* d_out, int out_size)
{
    (void)in_sizes; (void)n_in; (void)out_size;
    const float* states = (const float*)d_in[0];
    const float* action = (const float*)d_in[1];
    const int*   dones  = (const int*)d_in[2];
    const float* Wfe = (const float*)d_in[3];
    const float* bfe = (const float*)d_in[4];
    const float* Wih0 = (const float*)d_in[5];
    const float* Whh0 = (const float*)d_in[6];
    const float* bih0 = (const float*)d_in[7];
    const float* bhh0 = (const float*)d_in[8];
    const float* Wih1 = (const float*)d_in[9];
    const float* Whh1 = (const float*)d_in[10];
    const float* bih1 = (const float*)d_in[11];
    const float* bhh1 = (const float*)d_in[12];
    const float* Wf1 = (const float*)d_in[13];
    const float* bf1 = (const float*)d_in[14];
    const float* Wf2 = (const float*)d_in[15];
    const float* bf2 = (const float*)d_in[16];
    const float* Wm1 = (const float*)d_in[17];
    const float* bm1 = (const float*)d_in[18];
    const float* Wm2 = (const float*)d_in[19];
    const float* bm2 = (const float*)d_in[20];
    const float* Ws1 = (const float*)d_in[21];
    const float* bs1 = (const float*)d_in[22];
    const float* Ws2 = (const float*)d_in[23];
    const float* bs2 = (const float*)d_in[24];
    float* out = (float*)d_out;

    float *feats, *xw, *H0, *H1, *C0, *C1, *pred, *hidA, *hidB, *pfl, *pil;
    cudaGetSymbolAddress((void**)&feats, g_feats);
    cudaGetSymbolAddress((void**)&xw, g_xw);
    cudaGetSymbolAddress((void**)&H0, g_H0);
    cudaGetSymbolAddress((void**)&H1, g_outs);
    cudaGetSymbolAddress((void**)&C0, g_C0);
    cudaGetSymbolAddress((void**)&C1, g_C1);
    cudaGetSymbolAddress((void**)&pred, g_pred);
    cudaGetSymbolAddress((void**)&hidA, g_hidA);
    cudaGetSymbolAddress((void**)&hidB, g_hidB);
    cudaGetSymbolAddress((void**)&pfl, g_pfl);
    cudaGetSymbolAddress((void**)&pil, g_pil);

    cudaFuncSetAttribute(inv_kernel, cudaFuncAttributeMaxDynamicSharedMemorySize, 32840 * 4);

    // reset queue/flags; bucketing; tile lists
    init_kernel<<<32, 512>>>();
    bucket_count<<<1, 512>>>(dones);
    bucket_scan<<<1, 32>>>();
    bucket_fill<<<257, 512>>>();
    rowtile_init<<<257, 512>>>();
    tile_fill<<<258, 256>>>();

    // feature encoder: feats = relu(states @ Wfe^T + bfe)
    gemm_kernel<1><<<dim3(RALL / 128, HSV / 128), 256>>>(
        states, SDV, nullptr, Wfe, bfe, feats, RALL, HSV, SDV);

    // xw0 = feats @ Wih0^T + bih0 (all steps)
    gemm_kernel<0><<<dim3(RALL / 128, 1024 / 128), 256>>>(
        feats, HSV, nullptr, Wih0, bih0, xw, RALL, 1024, HSV);

    // -------- layer 0: wave0 elementwise + single DAG launch --------
    lstm_wave0<<<512, 256>>>(H0, C0, xw, bhh0);
    lstm_dag<<<DAGGRID, 256>>>(0, H0, C0, xw, Whh0, bhh0);

    // xw1 = H0 @ Wih1^T + bih1 (reuse xw buffer)
    gemm_kernel<0><<<dim3(RALL / 128, 1024 / 128), 256>>>(
        H0, SFV, nullptr, Wih1, bih1, xw, RALL, 1024, SFV);

    // -------- layer 1: wave0 elementwise + single DAG launch --------
    lstm_wave0<<<512, 256>>>(H1, C1, xw, bhh1);
    lstm_dag<<<DAGGRID, 256>>>(1, H1, C1, xw, Whh1, bhh1);

    // forward model
    gemm_kernel<1><<<dim3(R2 / 128, HSV / 128), 256>>>(
        H1, SFV, action, Wf1, bf1, hidA, R2, HSV, SFV + ADV);
    gemm_kernel<0><<<dim3(R2 / 128, SFV / 128), 256>>>(
        hidA, HSV, nullptr, Wf2, bf2, pred, R2, SFV, HSV);

    // forward loss + intrinsic reward
    floss_kernel<<<2048, 256>>>(pred, H1, out + 2, pfl);

    // inverse model hiddens
    gemm_kernel<1><<<dim3(R2 / 128, HSV / 128), 256>>>(
        H1, SFV, pred, Wm1, bm1, hidA, R2, HSV, 2 * SFV);
    gemm_kernel<1><<<dim3(R2 / 128, HSV / 128), 256>>>(
        H1, SFV, pred, Ws1, bs1, hidB, R2, HSV, 2 * SFV);

    // mu/std + inverse-loss partials
    inv_kernel<<<512, 256, 32840 * 4>>>(hidA, hidB, Wm2, bm2, Ws2, bs2, action, pil);

    // scalars
    final_reduce_kernel<<<1, 256>>>(pfl, pil, out);

    // hidden = [h0_T, h1_T, c0_T, c1_T]
    hid_copy<<<256, 512>>>(H0, H1, C0, C1, out + 2 + 131072);
}

// round 14
// speedup vs baseline: 1.6227x; 1.1045x over previous
#include <cuda_runtime.h>
#include <cuda_bf16.h>
#include <mma.h>
#include <math.h>

using namespace nvcuda;

#define T1V 257
#define BATCH 512
#define SDV 128
#define ADV 32
#define HSV 512
#define SFV 256
#define R2 131072    // 256*512 rows
#define RALL 131584  // 257*512 rows
#define MAXTILES 4096
#define DAGGRID 1024

// ---------------- scratch (__device__ globals; no runtime allocation) ----------------
__device__ float g_feats[(size_t)T1V * BATCH * HSV];
__device__ float g_xw   [(size_t)RALL * 1024];       // xw0/xw1, then reused as fwd hidA
__device__ float g_H0   [(size_t)RALL * SFV];
__device__ float g_outs [(size_t)RALL * SFV];
__device__ float g_C0   [(size_t)RALL * SFV];
__device__ float g_C1   [(size_t)RALL * SFV];
__device__ float g_pred [(size_t)R2 * SFV];
__device__ float g_hidAB[(size_t)R2 * 1024];         // [mu-hid | std-hid] fp32
__device__ __nv_bfloat16 g_outsb[(size_t)RALL * SFV];
__device__ __nv_bfloat16 g_predb[(size_t)R2 * SFV];
__device__ __nv_bfloat16 g_Winvb[1024 * 512];
__device__ float g_binv [1024];
__device__ float g_pfl  [2048];
__device__ float g_pil  [512];
__device__ int   g_off  [RALL];
__device__ int   g_cnt  [260];
__device__ int   g_base [260];
__device__ int   g_cur  [260];
__device__ int   g_idx  [RALL];
__device__ int   g_rowtile [RALL];
__device__ int   g_tilebase[260];
__device__ int   g_tiledesc[MAXTILES];
__device__ int   g_tilerows[MAXTILES];
__device__ int   g_tilek   [MAXTILES];
__device__ int   g_ntile;
__device__ int   g_qh[2];
__device__ int   g_tilecnt [2 * MAXTILES];
__device__ int   g_tiledone[2 * MAXTILES];

__device__ __forceinline__ float sigmoidf_(float x) { return 1.0f / (1.0f + expf(-x)); }

// ---------------- bucketing: count + scan + tile descs + flag init (ONE block) ----------
__global__ void count_scan_kernel(const int* __restrict__ dones) {
    __shared__ int sc[260];
    __shared__ int sbase[260], stb[260];
    const int b = threadIdx.x;                 // 512 threads
    if (b < 260) sc[b] = 0;
    __syncthreads();
    int off = 0;
    for (int t = 0; t < T1V; t++) {
        int r = t * BATCH + b;
        if (t == 0 || dones[r]) off = 0; else off++;
        g_off[r] = off;
        atomicAdd(&sc[off], 1);
    }
    __syncthreads();
    if (b == 0) {
        int s = 0, tb = 0;
        for (int k = 0; k < 258; k++) {
            g_cnt[k] = sc[k];
            g_base[k] = s; g_cur[k] = s; sbase[k] = s; s += sc[k];
            g_tilebase[k] = tb; stb[k] = tb;
            tb += (sc[k] + 63) >> 6;
        }
        g_ntile = tb;
    }
    __syncthreads();
    if (b < 258) {
        int cnt = sc[b], tb0 = stb[b], base = sbase[b];
        int ntk = (cnt + 63) >> 6;
        for (int j = 0; j < ntk; j++) {
            g_tiledesc[tb0 + j] = base + (j << 6);
            int rem = cnt - (j << 6);
            g_tilerows[tb0 + j] = rem < 64 ? rem : 64;
            g_tilek[tb0 + j] = b;
        }
    }
    for (int i = b; i < 2 * MAXTILES; i += 512) { g_tilecnt[i] = 0; g_tiledone[i] = 0; }
    if (b < 2) g_qh[b] = 0;
}

__global__ void bucket_fill() {
    int r = blockIdx.x * 512 + threadIdx.x;    // 257 x 512
    int k = g_off[r];
    int p = atomicAdd(&g_cur[k], 1);
    g_idx[p] = r;
    g_rowtile[r] = g_tilebase[k] + ((p - g_base[k]) >> 6);
}

// ---------------- DAG executor: ALL waves (incl. wave 0) of one layer ----------------
__global__ __launch_bounds__(256) void lstm_dag(
    int layer,
    float* __restrict__ H, float* __restrict__ C,
    __nv_bfloat16* __restrict__ Hb,
    const float* __restrict__ xw,
    const float* __restrict__ Whh, const float* __restrict__ bhh)
{
    __shared__ float as_[16][68];
    __shared__ float ws_[16][132];
    __shared__ int ridx[64];
    __shared__ int sh_e;

    const int tid = threadIdx.x;
    const int nent = g_ntile * 8;
    int* qh = &g_qh[layer];
    int* tcnt = g_tilecnt + layer * MAXTILES;
    volatile int* tdone = (volatile int*)(g_tiledone + layer * MAXTILES);

    const int mi = tid >> 4, ni = tid & 15;
    const int lrow = tid >> 2, lk = (tid & 3) * 4;
    const int wc = tid >> 1, wk = (tid & 1) * 8;
    const int wunit = wc >> 2, wgate = wc & 3;

    while (true) {
        __syncthreads();
        if (tid == 0) sh_e = atomicAdd(qh, 1);
        __syncthreads();
        const int e = sh_e;
        if (e >= nent) break;
        const int tile = e >> 3;
        const int u0 = (e & 7) << 5;
        const int start = g_tiledesc[tile];
        const int rows = g_tilerows[tile];
        const int wave = g_tilek[tile];

        if (wave == 0) {
            for (int idx = tid; idx < rows * 32; idx += 256) {
                int r = g_idx[start + (idx >> 5)];
                int u = u0 + (idx & 31);
                const float* x = xw + (size_t)r * 1024;
                float pi = x[u]       + bhh[u];
                float pg = x[512 + u] + bhh[512 + u];
                float po = x[768 + u] + bhh[768 + u];
                float c2 = sigmoidf_(pi) * tanhf(pg);
                float h2 = sigmoidf_(po) * tanhf(c2);
                C[(size_t)r * SFV + u] = c2;
                H[(size_t)r * SFV + u] = h2;
                if (Hb) Hb[(size_t)r * SFV + u] = __float2bfloat16(h2);
            }
        } else {
            if (tid < 64) {
                int m = tid < rows ? tid : 0;
                ridx[tid] = g_idx[start + m];
            }
            __syncthreads();
            if (tid < 64) {
                int pt = g_rowtile[ridx[tid] - BATCH];
                while (tdone[pt] == 0) __nanosleep(64);
            }
            __threadfence();
            __syncthreads();

            const float* Wr = Whh + (size_t)((wgate << 8) + u0 + wunit) * SFV;
            const float* Ar = H + (size_t)(ridx[lrow] - BATCH) * SFV;

            float acc[4][8];
#pragma unroll
            for (int i = 0; i < 4; i++)
#pragma unroll
                for (int j = 0; j < 8; j++) acc[i][j] = 0.f;

            for (int kc = 0; kc < SFV; kc += 16) {
                float4 av = *(const float4*)(Ar + kc + lk);
                float4 w0 = *(const float4*)(Wr + kc + wk);
                float4 w1 = *(const float4*)(Wr + kc + wk + 4);
                as_[lk + 0][lrow] = av.x; as_[lk + 1][lrow] = av.y;
                as_[lk + 2][lrow] = av.z; as_[lk + 3][lrow] = av.w;
                ws_[wk + 0][wc] = w0.x; ws_[wk + 1][wc] = w0.y;
                ws_[wk + 2][wc] = w0.z; ws_[wk + 3][wc] = w0.w;
                ws_[wk + 4][wc] = w1.x; ws_[wk + 5][wc] = w1.y;
                ws_[wk + 6][wc] = w1.z; ws_[wk + 7][wc] = w1.w;
                __syncthreads();
#pragma unroll
                for (int kk = 0; kk < 16; kk++) {
                    float4 a4 = *(const float4*)&as_[kk][mi << 2];
                    float4 wa = *(const float4*)&ws_[kk][ni << 2];
                    float4 wb = *(const float4*)&ws_[kk][(16 + ni) << 2];
                    float aa[4] = {a4.x, a4.y, a4.z, a4.w};
#pragma unroll
                    for (int i = 0; i < 4; i++) {
                        acc[i][0] += aa[i] * wa.x; acc[i][1] += aa[i] * wa.y;
                        acc[i][2] += aa[i] * wa.z; acc[i][3] += aa[i] * wa.w;
                        acc[i][4] += aa[i] * wb.x; acc[i][5] += aa[i] * wb.y;
                        acc[i][6] += aa[i] * wb.z; acc[i][7] += aa[i] * wb.w;
                    }
                }
                __syncthreads();
            }

#pragma unroll
            for (int i = 0; i < 4; i++) {
                const int r = ridx[(mi << 2) + i];
                const float* xr = xw + (size_t)r * 1024;
                const float* cp = C + (size_t)(r - BATCH) * SFV;
#pragma unroll
                for (int u2 = 0; u2 < 2; u2++) {
                    const int u = u0 + ni + (u2 << 4);
                    const int j0 = u2 << 2;
                    float pi = acc[i][j0 + 0] + xr[u]       + bhh[u];
                    float pf = acc[i][j0 + 1] + xr[256 + u] + bhh[256 + u];
                    float pg = acc[i][j0 + 2] + xr[512 + u] + bhh[512 + u];
                    float po = acc[i][j0 + 3] + xr[768 + u] + bhh[768 + u];
                    float c2 = sigmoidf_(pf) * cp[u] + sigmoidf_(pi) * tanhf(pg);
                    float h2 = sigmoidf_(po) * tanhf(c2);
                    C[(size_t)r * SFV + u] = c2;
                    H[(size_t)r * SFV + u] = h2;
                    if (Hb) Hb[(size_t)r * SFV + u] = __float2bfloat16(h2);
                }
            }
        }

        __threadfence();
        __syncthreads();
        if (tid == 0) {
            int old = atomicAdd(&tcnt[tile], 1);
            if (old == 7) atomicExch((int*)&tdone[tile], 1);
        }
    }
}

// ---------------- generic fp32 SGEMM (optional bf16 dual-write) ----------------
#define KC 16
template <int ACT, bool WB16>
__global__ __launch_bounds__(256) void gemm_kernel(
    const float* __restrict__ A1, int K1,
    const float* __restrict__ A2,
    const float* __restrict__ W,
    const float* __restrict__ bias,
    float* __restrict__ C, __nv_bfloat16* __restrict__ Cb,
    int M, int N, int K)
{
    __shared__ float as_[KC][132];
    __shared__ float bs_[KC][132];
    const int m0 = blockIdx.x * 128;
    const int n0 = blockIdx.y * 128;
    const int tid = threadIdx.x;
    const int mi = tid >> 4;
    const int ni = tid & 15;
    const int lrow = tid >> 2;
    const int lk = (tid & 3) * 4;

    float acc[8][8];
#pragma unroll
    for (int i = 0; i < 8; i++)
#pragma unroll
        for (int j = 0; j < 8; j++) acc[i][j] = 0.f;

    for (int kc = 0; kc < K; kc += KC) {
        const float* Asrc;
        int Ak, koff;
        if (kc < K1) { Asrc = A1; Ak = K1; koff = kc; }
        else         { Asrc = A2; Ak = K - K1; koff = kc - K1; }
#pragma unroll
        for (int r = 0; r < 2; r++) {
            int row = lrow + r * 64;
            float4 v = *(const float4*)(Asrc + (size_t)(m0 + row) * Ak + koff + lk);
            as_[lk + 0][row] = v.x; as_[lk + 1][row] = v.y;
            as_[lk + 2][row] = v.z; as_[lk + 3][row] = v.w;
            float4 w = *(const float4*)(W + (size_t)(n0 + row) * K + kc + lk);
            bs_[lk + 0][row] = w.x; bs_[lk + 1][row] = w.y;
            bs_[lk + 2][row] = w.z; bs_[lk + 3][row] = w.w;
        }
        __syncthreads();
#pragma unroll
        for (int k = 0; k < KC; k++) {
            float4 a0 = *(const float4*)&as_[k][mi * 8];
            float4 a1 = *(const float4*)&as_[k][mi * 8 + 4];
            float a[8] = {a0.x, a0.y, a0.z, a0.w, a1.x, a1.y, a1.z, a1.w};
            float b[8];
#pragma unroll
            for (int j = 0; j < 8; j++) b[j] = bs_[k][ni + j * 16];
#pragma unroll
            for (int i = 0; i < 8; i++)
#pragma unroll
                for (int j = 0; j < 8; j++) acc[i][j] += a[i] * b[j];
        }
        __syncthreads();
    }
#pragma unroll
    for (int i = 0; i < 8; i++) {
        int row = m0 + mi * 8 + i;
#pragma unroll
        for (int j = 0; j < 8; j++) {
            int col = n0 + ni + j * 16;
            float v = acc[i][j] + bias[col];
            if (ACT == 1) v = fmaxf(v, 0.f);
            C[(size_t)row * N + col] = v;
            if (WB16) Cb[(size_t)row * N + col] = __float2bfloat16(v);
        }
    }
}

// ---------------- bf16 WMMA GEMM: C = act(A @ W^T + bias), fp32 out ----------------
template <int ACT>
__global__ __launch_bounds__(256) void wmma_gemm(
    const __nv_bfloat16* __restrict__ A1, int K1,
    const __nv_bfloat16* __restrict__ A2,
    const __nv_bfloat16* __restrict__ W,
    const float* __restrict__ bias,
    float* __restrict__ Cf,
    int M, int N, int K)
{
    __shared__ __align__(16) char raw[36864];
    __nv_bfloat16 (*As)[40] = (__nv_bfloat16(*)[40])raw;
    __nv_bfloat16 (*Bs)[40] = (__nv_bfloat16(*)[40])(raw + 10240);

    const int tid = threadIdx.x, warp = tid >> 5, lane = tid & 31;
    const int m0 = blockIdx.x * 128, n0 = blockIdx.y * 64;
    const int wm = warp >> 1, wn = warp & 1;
    const int arow = tid >> 1, ahalf = (tid & 1) * 16;

    wmma::fragment<wmma::accumulator, 16, 16, 16, float> acc[2][2];
#pragma unroll
    for (int i = 0; i < 2; i++)
#pragma unroll
        for (int j = 0; j < 2; j++) wmma::fill_fragment(acc[i][j], 0.f);

    for (int kc = 0; kc < K; kc += 32) {
        const __nv_bfloat16* src; int wsrc, koff;
        if (kc < K1) { src = A1; wsrc = K1; koff = kc; }
        else         { src = A2; wsrc = K - K1; koff = kc - K1; }
        const uint4* ap = (const uint4*)(src + (size_t)(m0 + arow) * wsrc + koff + ahalf);
        uint4 a0v = ap[0], a1v = ap[1];
        *(uint4*)(&As[arow][ahalf])     = a0v;
        *(uint4*)(&As[arow][ahalf + 8]) = a1v;
        if (tid < 128) {
            const int brow = tid >> 1, bhalf = (tid & 1) * 16;
            const uint4* bp = (const uint4*)(W + (size_t)(n0 + brow) * K + kc + bhalf);
            uint4 b0v = bp[0], b1v = bp[1];
            *(uint4*)(&Bs[brow][bhalf])     = b0v;
            *(uint4*)(&Bs[brow][bhalf + 8]) = b1v;
        }
        __syncthreads();

        wmma::fragment<wmma::matrix_a, 16, 16, 16, __nv_bfloat16, wmma::row_major> aF[2], aG[2];
        wmma::fragment<wmma::matrix_b, 16, 16, 16, __nv_bfloat16, wmma::col_major> bF[2], bG[2];
#pragma unroll
        for (int i = 0; i < 2; i++) {
            wmma::load_matrix_sync(aF[i], &As[wm * 32 + i * 16][0], 40);
            wmma::load_matrix_sync(aG[i], &As[wm * 32 + i * 16][16], 40);
        }
#pragma unroll
        for (int j = 0; j < 2; j++) {
            wmma::load_matrix_sync(bF[j], &Bs[wn * 32 + j * 16][0], 40);
            wmma::load_matrix_sync(bG[j], &Bs[wn * 32 + j * 16][16], 40);
        }
#pragma unroll
        for (int i = 0; i < 2; i++)
#pragma unroll
            for (int j = 0; j < 2; j++) {
                wmma::mma_sync(acc[i][j], aF[i], bF[j], acc[i][j]);
                wmma::mma_sync(acc[i][j], aG[i], bG[j], acc[i][j]);
            }
        __syncthreads();
    }

    __syncthreads();
    float* mysc = (float*)raw + warp * (32 * 36);
#pragma unroll
    for (int i = 0; i < 2; i++)
#pragma unroll
        for (int j = 0; j < 2; j++)
            wmma::store_matrix_sync(mysc + i * 16 * 36 + j * 16, acc[i][j], 36, wmma::mem_row_major);
    __syncwarp();
    const int gm = m0 + wm * 32 + lane;
    const int gc0 = n0 + wn * 32;
#pragma unroll 8
    for (int c = 0; c < 32; c++) {
        float v = mysc[lane * 36 + c] + bias[gc0 + c];
        if (ACT == 1) v = fmaxf(v, 0.f);
        Cf[(size_t)gm * N + gc0 + c] = v;
    }
}

// ---------------- convert: fused inverse weights/bias to bf16 ----------------
__global__ void convert_kernel(const float* __restrict__ Wm1, const float* __restrict__ Ws1,
                               const float* __restrict__ bm1, const float* __restrict__ bs1)
{
    const int S3 = 1024 * 512;
    int i = blockIdx.x * blockDim.x + threadIdx.x;
    if (i < S3)
        g_Winvb[i] = __float2bfloat16(i < 262144 ? Wm1[i] : Ws1[i - 262144]);
    else if (i < S3 + 1024) {
        int j = i - S3;
        g_binv[j] = j < 512 ? bm1[j] : bs1[j - 512];
    }
}

// ---------------- forward loss + intrinsic reward ----------------
__global__ void floss_kernel(const float* __restrict__ pred, const float* __restrict__ outs,
                             float* __restrict__ intr, float* __restrict__ pfl)
{
    const int w = threadIdx.x >> 5, lane = threadIdx.x & 31;
    const int r0 = blockIdx.x * 64;
    __shared__ float sred[8];
    float wacc = 0.f;
    for (int p = 0; p < 8; p++) {
        int r = r0 + p * 8 + w;
        const float4* pp = (const float4*)(pred + (size_t)r * SFV) + lane * 2;
        const float4* np = (const float4*)(outs + (size_t)(r + BATCH) * SFV) + lane * 2;
        float4 p0 = pp[0], p1 = pp[1], n0 = np[0], n1 = np[1];
        float d0 = p0.x - n0.x, d1 = p0.y - n0.y, d2 = p0.z - n0.z, d3 = p0.w - n0.w;
        float d4 = p1.x - n1.x, d5 = p1.y - n1.y, d6 = p1.z - n1.z, d7 = p1.w - n1.w;
        float s = d0 * d0 + d1 * d1 + d2 * d2 + d3 * d3 + d4 * d4 + d5 * d5 + d6 * d6 + d7 * d7;
#pragma unroll
        for (int o = 16; o; o >>= 1) s += __shfl_xor_sync(0xffffffffu, s, o);
        if (lane == 0) { intr[r] = s; wacc += s; }
    }
    if (lane == 0) sred[w] = wacc;
    __syncthreads();
    if (threadIdx.x == 0) {
        float t = 0.f;
        for (int i = 0; i < 8; i++) t += sred[i];
        pfl[blockIdx.x] = t;
    }
}

// ---------------- inverse head: mu/std + NLL partials (reads fused hidAB) ----------------
__global__ void inv_kernel(const float* __restrict__ hAB,
                           const float* __restrict__ Wm2, const float* __restrict__ bm2,
                           const float* __restrict__ Ws2, const float* __restrict__ bs2,
                           const float* __restrict__ act, float* __restrict__ pil)
{
    extern __shared__ float sh[];
    float* wm = sh;
    float* ws2s = sh + 16384;
    float* bm = sh + 32768;
    float* bs = sh + 32800;
    float* red = sh + 32832;
    const int tid = threadIdx.x;
    for (int idx = tid; idx < 16384; idx += 256) {
        int d = idx & 31, k = idx >> 5;
        wm[idx] = Wm2[(size_t)d * HSV + k];
        ws2s[idx] = Ws2[(size_t)d * HSV + k];
    }
    if (tid < 32) { bm[tid] = bm2[tid]; bs[tid] = bs2[tid]; }
    __syncthreads();

    const int w = tid >> 5, lane = tid & 31;
    const int r0 = blockIdx.x * 256;
    float ilacc = 0.f;
    for (int p = 0; p < 32; p++) {
        int r = r0 + p * 8 + w;
        const float4* h4m = (const float4*)(hAB + (size_t)r * 1024);
        const float4* h4s = (const float4*)(hAB + (size_t)r * 1024 + 512);
        float am = 0.f, as2 = 0.f;
#pragma unroll 4
        for (int k4 = 0; k4 < 128; k4++) {
            float4 a = h4m[k4];
            float4 b = h4s[k4];
            int kb = k4 * 128 + lane;
            am  += a.x * wm[kb] + a.y * wm[kb + 32] + a.z * wm[kb + 64] + a.w * wm[kb + 96];
            as2 += b.x * ws2s[kb] + b.y * ws2s[kb + 32] + b.z * ws2s[kb + 64] + b.w * ws2s[kb + 96];
        }
        float mu = tanhf(am + bm[lane]);
        float sv = as2 + bs[lane];
        float sd = fmaxf(sv, 0.f) + log1pf(expf(-fabsf(sv)));
        float a_ = act[(size_t)r * ADV + lane];
        float z = (a_ - mu) / sd;
        ilacc += 0.5f * z * z + logf(sd) + 0.91893853320467274f;
    }
#pragma unroll
    for (int o = 16; o; o >>= 1) ilacc += __shfl_xor_sync(0xffffffffu, ilacc, o);
    if (lane == 0) red[w] = ilacc;
    __syncthreads();
    if (tid == 0) {
        float t = 0.f;
        for (int i = 0; i < 8; i++) t += red[i];
        pil[blockIdx.x] = t;
    }
}

// ---------------- final scalar reduce ----------------
__global__ void final_reduce_kernel(const float* __restrict__ pfl, const float* __restrict__ pil,
                                    float* __restrict__ out)
{
    __shared__ float s1[256], s2[256];
    int tid = threadIdx.x;
    float a = 0.f, b = 0.f;
    for (int i = tid; i < 2048; i += 256) a += pfl[i];
    for (int i = tid; i < 512; i += 256) b += pil[i];
    s1[tid] = a; s2[tid] = b;
    __syncthreads();
    for (int st = 128; st; st >>= 1) {
        if (tid < st) { s1[tid] += s1[tid + st]; s2[tid] += s2[tid + st]; }
        __syncthreads();
    }
    if (tid == 0) {
        out[0] = s1[0] / 33554432.f;
        out[1] = s2[0] / 4194304.f;
    }
}

// ---------------- hidden copy ----------------
__global__ void hid_copy(const float* __restrict__ H0, const float* __restrict__ H1,
                         const float* __restrict__ C0, const float* __restrict__ C1,
                         float* __restrict__ hid)
{
    int i = blockIdx.x * blockDim.x + threadIdx.x;  // 131072
    const size_t o = (size_t)131072 * 256 + i;       // rows t=256
    hid[i]          = H0[o];
    hid[131072 + i] = H1[o];
    hid[262144 + i] = C0[o];
    hid[393216 + i] = C1[o];
}

// ---------------- host orchestration ----------------
extern "C" void kernel_launch(void* const* d_in, const int* in_sizes, int n_in,
                              void* d_out, int out_size)
{
    (void)in_sizes; (void)n_in; (void)out_size;
    const float* states = (const float*)d_in[0];
    const float* action = (const float*)d_in[1];
    const int*   dones  = (const int*)d_in[2];
    const float* Wfe = (const float*)d_in[3];
    const float* bfe = (const float*)d_in[4];
    const float* Wih0 = (const float*)d_in[5];
    const float* bih0 = (const float*)d_in[7];
    const float* Whh0 = (const float*)d_in[6];
    const float* bhh0 = (const float*)d_in[8];
    const float* Wih1 = (const float*)d_in[9];
    const float* Whh1 = (const float*)d_in[10];
    const float* bih1 = (const float*)d_in[11];
    const float* bhh1 = (const float*)d_in[12];
    const float* Wf1 = (const float*)d_in[13];
    const float* bf1 = (const float*)d_in[14];
    const float* Wf2 = (const float*)d_in[15];
    const float* bf2 = (const float*)d_in[16];
    const float* Wm1 = (const float*)d_in[17];
    const float* bm1 = (const float*)d_in[18];
    const float* Wm2 = (const float*)d_in[19];
    const float* bm2 = (const float*)d_in[20];
    const float* Ws1 = (const float*)d_in[21];
    const float* bs1 = (const float*)d_in[22];
    const float* Ws2 = (const float*)d_in[23];
    const float* bs2 = (const float*)d_in[24];
    float* out = (float*)d_out;

    float *feats, *xw, *H0, *H1, *C0, *C1, *pred, *hidAB, *binv, *pfl, *pil;
    __nv_bfloat16 *outsb, *predb, *Winvb;
    cudaGetSymbolAddress((void**)&feats, g_feats);
    cudaGetSymbolAddress((void**)&xw, g_xw);
    cudaGetSymbolAddress((void**)&H0, g_H0);
    cudaGetSymbolAddress((void**)&H1, g_outs);
    cudaGetSymbolAddress((void**)&C0, g_C0);
    cudaGetSymbolAddress((void**)&C1, g_C1);
    cudaGetSymbolAddress((void**)&pred, g_pred);
    cudaGetSymbolAddress((void**)&hidAB, g_hidAB);
    cudaGetSymbolAddress((void**)&binv, g_binv);
    cudaGetSymbolAddress((void**)&pfl, g_pfl);
    cudaGetSymbolAddress((void**)&pil, g_pil);
    cudaGetSymbolAddress((void**)&outsb, g_outsb);
    cudaGetSymbolAddress((void**)&predb, g_predb);
    cudaGetSymbolAddress((void**)&Winvb, g_Winvb);

    cudaFuncSetAttribute(inv_kernel, cudaFuncAttributeMaxDynamicSharedMemorySize, 32840 * 4);

    // 1: feature encoder (fp32)
    gemm_kernel<1, false><<<dim3(RALL / 128, HSV / 128), 256>>>(
        states, SDV, nullptr, Wfe, bfe, feats, nullptr, RALL, HSV, SDV);
    // 2: xw0 = feats @ Wih0^T + bih0 (fp32)
    gemm_kernel<0, false><<<dim3(RALL / 128, 1024 / 128), 256>>>(
        feats, HSV, nullptr, Wih0, bih0, xw, nullptr, RALL, 1024, HSV);
    // 3-4: bucketing
    count_scan_kernel<<<1, 512>>>(dones);
    bucket_fill<<<257, 512>>>();
    // 5: bf16 conversion (fused inverse weights + bias)
    convert_kernel<<<(1024 * 512 + 1024 + 511) / 512, 512>>>(Wm1, Ws1, bm1, bs1);
    // 6: layer-0 DAG  (ncu -s 5 -c 1 profiles this launch)
    lstm_dag<<<DAGGRID, 256>>>(0, H0, C0, nullptr, xw, Whh0, bhh0);
    // 7: xw1 = H0 @ Wih1^T + bih1 (fp32)
    gemm_kernel<0, false><<<dim3(RALL / 128, 1024 / 128), 256>>>(
        H0, SFV, nullptr, Wih1, bih1, xw, nullptr, RALL, 1024, SFV);
    // 8: layer-1 DAG (writes fp32 + bf16 h1)
    lstm_dag<<<DAGGRID, 256>>>(1, H1, C1, outsb, xw, Whh1, bhh1);

    // 9: fwd hidden (fp32; reuse xw buffer as hidA scratch)
    gemm_kernel<1, false><<<dim3(R2 / 128, HSV / 128), 256>>>(
        H1, SFV, action, Wf1, bf1, xw, nullptr, R2, HSV, SFV + ADV);
    // 10: pred (fp32 + bf16 dual write)
    gemm_kernel<0, true><<<dim3(R2 / 128, SFV / 128), 256>>>(
        xw, HSV, nullptr, Wf2, bf2, pred, predb, R2, SFV, HSV);
    // 11: forward loss + intrinsic reward
    floss_kernel<<<2048, 256>>>(pred, H1, out + 2, pfl);
    // 12: fused inverse hiddens via bf16 WMMA (mu-hid | std-hid), fp32 out
    wmma_gemm<1><<<dim3(R2 / 128, 1024 / 64), 256>>>(
        outsb, SFV, predb, Winvb, binv, hidAB, R2, 1024, 2 * SFV);
    // 13: mu/std + NLL partials
    inv_kernel<<<512, 256, 32840 * 4>>>(hidAB, Wm2, bm2, Ws2, bs2, action, pil);
    // 14: scalars
    final_reduce_kernel<<<1, 256>>>(pfl, pil, out);
    // 15: hidden
    hid_copy<<<256, 512>>>(H0, H1, C0, C1, out + 2 + 131072);
}